// round 5
// baseline (speedup 1.0000x reference)
#include <cuda_runtime.h>
#include <math.h>

// ---------------------------------------------------------------------------
// Problem constants
// ---------------------------------------------------------------------------
#define DW 128
#define DH 128
#define DD 128
#define NV (DW*DH*DD)          // 2097152 voxels
#define NS 16
#define HSL 128
#define WSL 128
#define PIX (HSL*WSL)
#define RES 1.5f
#define INV_RES 0.6666666667f
#define N_ITER 10

// ---------------------------------------------------------------------------
// Persistent state (device globals -> no allocations anywhere)
// ---------------------------------------------------------------------------
__device__ float g_b[NV];
__device__ float g_x[NV];
__device__ float g_r[NV];
__device__ float g_p[NV];          // materialized p (p_prev for next iter)
__device__ float g_sl[NS*PIX];     // slice-space scratch: A applied to a volume
// per-iteration CG scalars (double accumulators)
__device__ double g_pAp[16];
__device__ double g_rr[16];

// ---------------------------------------------------------------------------
// Block reduction -> atomicAdd(double)
// ---------------------------------------------------------------------------
__device__ __forceinline__ void reduce_add(double val, double* target)
{
    #pragma unroll
    for (int o = 16; o > 0; o >>= 1)
        val += __shfl_down_sync(0xffffffffu, val, o);
    __shared__ double sm[32];
    int lane = threadIdx.x & 31, wid = threadIdx.x >> 5;
    if (lane == 0) sm[wid] = val;
    __syncthreads();
    if (wid == 0) {
        val = (lane < (int)(blockDim.x >> 5)) ? sm[lane] : 0.0;
        #pragma unroll
        for (int o = 16; o > 0; o >>= 1)
            val += __shfl_down_sync(0xffffffffu, val, o);
        if (lane == 0) atomicAdd(target, val);
    }
}

// ---------------------------------------------------------------------------
// Forward (A): PSF-weighted trilinear gather.  Input vector is implicit:
// v = v1 + beta * g_p   (HASB) or just v1.
// ---------------------------------------------------------------------------
template<bool HASB>
__device__ __forceinline__ float fetch(const float* __restrict__ v1, float beta, int idx)
{
    float v = __ldg(v1 + idx);
    if (HASB) v += beta * __ldg(&g_p[idx]);
    return v;
}

template<bool HASB>
__device__ __forceinline__ float gather_tap(const float* __restrict__ v1, float beta,
                                            float px, float py, float pz)
{
    if (px <= -1.f || px >= 128.f || py <= -1.f || py >= 128.f ||
        pz <= -1.f || pz >= 128.f)
        return 0.f;

    float xf = floorf(px), yf = floorf(py), zf = floorf(pz);
    int ix = (int)xf, iy = (int)yf, iz = (int)zf;
    float fx = px - xf, fy = py - yf, fz = pz - zf;
    float gx = 1.f - fx, gy = 1.f - fy, gz = 1.f - fz;

    if (ix >= 0 && ix < DW-1 && iy >= 0 && iy < DH-1 && iz >= 0 && iz < DD-1) {
        int b0 = (iz*DH + iy)*DW + ix;
        int b1 = b0 + DH*DW;
        float v000 = fetch<HASB>(v1, beta, b0),      v100 = fetch<HASB>(v1, beta, b0+1);
        float v010 = fetch<HASB>(v1, beta, b0+DW),   v110 = fetch<HASB>(v1, beta, b0+DW+1);
        float v001 = fetch<HASB>(v1, beta, b1),      v101 = fetch<HASB>(v1, beta, b1+1);
        float v011 = fetch<HASB>(v1, beta, b1+DW),   v111 = fetch<HASB>(v1, beta, b1+DW+1);
        return gz*(gy*(gx*v000 + fx*v100) + fy*(gx*v010 + fx*v110))
             + fz*(gy*(gx*v001 + fx*v101) + fy*(gx*v011 + fx*v111));
    }

    float acc = 0.f;
    #pragma unroll
    for (int dz = 0; dz < 2; dz++)
    #pragma unroll
    for (int dy = 0; dy < 2; dy++)
    #pragma unroll
    for (int dx = 0; dx < 2; dx++) {
        int X = ix + dx, Y = iy + dy, Z = iz + dz;
        if (X >= 0 && X < DW && Y >= 0 && Y < DH && Z >= 0 && Z < DD) {
            float w = (dx ? fx : gx) * (dy ? fy : gy) * (dz ? fz : gz);
            acc += w * fetch<HASB>(v1, beta, (Z*DH + Y)*DW + X);
        }
    }
    return acc;
}

__device__ __forceinline__ void load_slice_consts(const float* __restrict__ theta,
                                                  const float* __restrict__ psf,
                                                  int n, float sR[9],
                                                  float sC[27][3], float sPsf[27])
{
    int t = threadIdx.x;
    if (t < 9) sR[t] = theta[n*12 + (t/3)*4 + (t%3)];
    __syncthreads();
    if (t < 27) {
        float ox = (float)(t % 3)       - 1.f;
        float oy = (float)((t / 3) % 3) - 1.f;
        float oz = (float)(t / 9)       - 1.f;
        float tx = theta[n*12 + 3],  ty = theta[n*12 + 7],  tz = theta[n*12 + 11];
        sC[t][0] = sR[0]*ox + sR[1]*oy + sR[2]*oz + tx + 63.5f;
        sC[t][1] = sR[3]*ox + sR[4]*oy + sR[5]*oz + ty + 63.5f;
        sC[t][2] = sR[6]*ox + sR[7]*oy + sR[8]*oz + tz + 63.5f;
        sPsf[t]  = psf[t];
    }
    __syncthreads();
}

// k_A: slices <- A(v),  g_sl[n,pix] = sval, g_pAp[slot] += sum(sval^2).
// grid = (64, 1, 16), block = 256.  ALL threads reach the reduction.
template<bool HASB>
__global__ void __launch_bounds__(256)
k_A(const float* __restrict__ theta, const float* __restrict__ psf,
    const float* __restrict__ v1, int beta_it, int pAp_slot)
{
    __shared__ float sR[9];
    __shared__ float sC[27][3];
    __shared__ float sPsf[27];
    int n = blockIdx.z;
    load_slice_consts(theta, psf, n, sR, sC, sPsf);

    float beta = 0.f;
    if (HASB) beta = (float)(g_rr[beta_it] / g_rr[beta_it - 1]);

    int pix = blockIdx.x * blockDim.x + threadIdx.x;
    int w = pix & (WSL-1);
    int h = pix >> 7;
    float u  = ((float)w - 63.5f) * RES;
    float vv = ((float)h - 63.5f) * RES;
    float bx = sR[0]*u + sR[1]*vv;
    float by = sR[3]*u + sR[4]*vv;
    float bz = sR[6]*u + sR[7]*vv;

    float sval = 0.f;
    // conservative whole-pixel reject: center tap within margin 3 of volume
    float cx = bx + sC[13][0], cy = by + sC[13][1], cz = bz + sC[13][2];
    if (cx > -3.f && cx < 130.f && cy > -3.f && cy < 130.f &&
        cz > -3.f && cz < 130.f) {
        for (int k = 0; k < 27; k++)
            sval += sPsf[k] * gather_tap<HASB>(v1, beta,
                        bx + sC[k][0], by + sC[k][1], bz + sC[k][2]);
    }
    g_sl[n * PIX + pix] = sval;
    reduce_add((double)sval * (double)sval, &g_pAp[pAp_slot]);
}

// ---------------------------------------------------------------------------
// Adjoint (At) as a pure GATHER over voxels: no atomics, no zeroing.
// For voxel X: enumerate all (slice n, pixel (i,j), tap off) whose trilinear
// footprint covers X:  s = base+off satisfies |s - q|_a <= m_a with
// q = R^T (X - T) and m_a = abs-column-sum_a of R.  Weight computed exactly
// as Prod_a max(0, 1 - |X_a - P_a|) via d = R e, e = q - s.
// ---------------------------------------------------------------------------
__device__ __forceinline__ void load_adj_consts(const float* __restrict__ theta,
                                                const float* __restrict__ psf,
                                                float sR[NS][9], float sT[NS][3],
                                                float sM[NS][3], float sPsf[27])
{
    int t = threadIdx.x;
    if (t < NS) {
        #pragma unroll
        for (int r = 0; r < 3; r++)
            #pragma unroll
            for (int c = 0; c < 3; c++)
                sR[t][r*3+c] = theta[t*12 + r*4 + c];
        sT[t][0] = theta[t*12 + 3]  + 63.5f;
        sT[t][1] = theta[t*12 + 7]  + 63.5f;
        sT[t][2] = theta[t*12 + 11] + 63.5f;
        // per-axis bound = abs column sum + eps
        sM[t][0] = fabsf(sR[t][0]) + fabsf(sR[t][3]) + fabsf(sR[t][6]) + 1e-3f;
        sM[t][1] = fabsf(sR[t][1]) + fabsf(sR[t][4]) + fabsf(sR[t][7]) + 1e-3f;
        sM[t][2] = fabsf(sR[t][2]) + fabsf(sR[t][5]) + fabsf(sR[t][8]) + 1e-3f;
    }
    if (t < 27) sPsf[t] = psf[t];
    __syncthreads();
}

__device__ __forceinline__ float adj_gather(const float* __restrict__ sl,
                                            int idx,
                                            const float sR[NS][9],
                                            const float sT[NS][3],
                                            const float sM[NS][3],
                                            const float sPsf[27])
{
    float X = (float)(idx & (DW-1));
    float Y = (float)((idx >> 7) & (DH-1));
    float Z = (float)(idx >> 14);

    float acc = 0.f;
    for (int n = 0; n < NS; n++) {
        const float* R = sR[n];
        float dx = X - sT[n][0], dy = Y - sT[n][1], dz = Z - sT[n][2];
        float qz = R[2]*dx + R[5]*dy + R[8]*dz;
        float mz = sM[n][2];
        if (fabsf(qz) >= 1.f + mz) continue;
        float qx = R[0]*dx + R[3]*dy + R[6]*dz;
        float qy = R[1]*dx + R[4]*dy + R[7]*dz;
        float mx = sM[n][0], my = sM[n][1];
        const float* sln = sl + n * PIX;

        // pixel index ranges per tap-offset component (indep of oz)
        int iR0[3], iR1[3], jR0[3], jR1[3];
        #pragma unroll
        for (int o = 0; o < 3; o++) {
            float exq = qx - ((float)o - 1.f);
            int i0 = (int)ceilf ((exq - mx)*INV_RES + 63.5f - 1e-3f);
            int i1 = (int)floorf((exq + mx)*INV_RES + 63.5f + 1e-3f);
            iR0[o] = i0 < 0 ? 0 : i0;  iR1[o] = i1 > 127 ? 127 : i1;
            float eyq = qy - ((float)o - 1.f);
            int j0 = (int)ceilf ((eyq - my)*INV_RES + 63.5f - 1e-3f);
            int j1 = (int)floorf((eyq + my)*INV_RES + 63.5f + 1e-3f);
            jR0[o] = j0 < 0 ? 0 : j0;  jR1[o] = j1 > 127 ? 127 : j1;
        }

        for (int ozi = 0; ozi < 3; ozi++) {
            float ez = qz - ((float)ozi - 1.f);
            if (fabsf(ez) > mz) continue;
            float az0 = R[2]*ez, az1 = R[5]*ez, az2 = R[8]*ez;
            int kz = ozi * 9;
            for (int oxi = 0; oxi < 3; oxi++) {
                float exq = qx - ((float)oxi - 1.f);
                for (int i = iR0[oxi]; i <= iR1[oxi]; i++) {
                    float ex = exq - ((float)i - 63.5f)*RES;
                    float b0 = az0 + R[0]*ex;
                    float b1 = az1 + R[3]*ex;
                    float b2 = az2 + R[6]*ex;
                    for (int oyi = 0; oyi < 3; oyi++) {
                        float eyq = qy - ((float)oyi - 1.f);
                        float pw = sPsf[kz + oyi*3 + oxi];
                        for (int j = jR0[oyi]; j <= jR1[oyi]; j++) {
                            float ey = eyq - ((float)j - 63.5f)*RES;
                            float d0 = b0 + R[1]*ey;
                            float d1 = b1 + R[4]*ey;
                            float d2 = b2 + R[7]*ey;
                            float w0 = 1.f - fabsf(d0);
                            float w1 = 1.f - fabsf(d1);
                            float w2 = 1.f - fabsf(d2);
                            if (fminf(w0, fminf(w1, w2)) > 0.f)
                                acc += w0*w1*w2 * pw * __ldg(sln + j*WSL + i);
                        }
                    }
                }
            }
        }
    }
    return acc;
}

// b = At(slices)
__global__ void __launch_bounds__(256)
k_Atg_b(const float* __restrict__ theta, const float* __restrict__ psf,
        const float* __restrict__ slices)
{
    __shared__ float sR[NS][9], sT[NS][3], sM[NS][3], sPsf[27];
    load_adj_consts(theta, psf, sR, sT, sM, sPsf);
    int idx = blockIdx.x * blockDim.x + threadIdx.x;
    g_b[idx] = adj_gather(slices, idx, sR, sT, sM, sPsf);
}

// r0 = b - At(A x0);  rr[0] += r0.r0
__global__ void __launch_bounds__(256)
k_Atg_init(const float* __restrict__ theta, const float* __restrict__ psf)
{
    __shared__ float sR[NS][9], sT[NS][3], sM[NS][3], sPsf[27];
    load_adj_consts(theta, psf, sR, sT, sM, sPsf);
    int idx = blockIdx.x * blockDim.x + threadIdx.x;
    float acc = adj_gather(g_sl, idx, sR, sT, sM, sPsf);
    float rv = g_b[idx] - acc;
    g_r[idx] = rv;
    reduce_add((double)rv * (double)rv, &g_rr[0]);
}

// Fused adjoint + CG update for iteration `it`:
//   Ap = At(g_sl);  alpha = rr[it]/pAp[it];  p_cur = r + beta*p_prev (beta from
//   rr slots, absent for it==0);  x += alpha*p_cur;  p = p_cur;
//   r -= alpha*Ap;  rr[it+1] += r.r
template<bool HASB>
__global__ void __launch_bounds__(256)
k_Atg_xr(const float* __restrict__ theta, const float* __restrict__ psf, int it)
{
    __shared__ float sR[NS][9], sT[NS][3], sM[NS][3], sPsf[27];
    load_adj_consts(theta, psf, sR, sT, sM, sPsf);
    int idx = blockIdx.x * blockDim.x + threadIdx.x;
    float acc = adj_gather(g_sl, idx, sR, sT, sM, sPsf);

    float alpha = (float)(g_rr[it] / g_pAp[it]);
    float rv = g_r[idx];
    float pc;
    if (HASB) {
        float beta = (float)(g_rr[it] / g_rr[it - 1]);
        pc = rv + beta * g_p[idx];
    } else {
        pc = rv;
    }
    g_x[idx] += alpha * pc;
    g_p[idx] = pc;
    rv -= alpha * acc;
    g_r[idx] = rv;
    reduce_add((double)rv * (double)rv, &g_rr[it + 1]);
}

// ---------------------------------------------------------------------------
// init + output
// ---------------------------------------------------------------------------
__global__ void __launch_bounds__(256)
k_init(const float* __restrict__ volume)
{
    int i = blockIdx.x * blockDim.x + threadIdx.x;
    if (i < NV) g_x[i] = volume[i];
    if (blockIdx.x == 0 && threadIdx.x < 16) {
        g_pAp[threadIdx.x] = 0.0;
        g_rr[threadIdx.x]  = 0.0;
    }
}

__global__ void __launch_bounds__(256)
k_relu_out(float* __restrict__ out)
{
    int i = blockIdx.x * blockDim.x + threadIdx.x;
    if (i < NV) out[i] = fmaxf(g_x[i], 0.f);
}

// ---------------------------------------------------------------------------
// Host driver (graph-capturable)
// ---------------------------------------------------------------------------
extern "C" void kernel_launch(void* const* d_in, const int* in_sizes, int n_in,
                              void* d_out, int out_size)
{
    const float *theta = nullptr, *slices = nullptr, *volume = nullptr, *psf = nullptr;
    for (int i = 0; i < n_in; i++) {
        switch (in_sizes[i]) {
            case NS*12:   theta  = (const float*)d_in[i]; break;
            case NS*PIX:  slices = (const float*)d_in[i]; break;
            case NV:      volume = (const float*)d_in[i]; break;
            case 27:      psf    = (const float*)d_in[i]; break;
            default: break;
        }
    }
    float* out = (float*)d_out;

    float *r;
    cudaGetSymbolAddress((void**)&r, g_r);

    const int VB = NV / 256;                       // 8192
    const dim3 gridS(PIX / 256, 1, NS);            // (64,1,16)

    // 0: x = x0, zero CG scalar slots
    k_init<<<VB, 256>>>(volume);
    // 1: b = At(slices)   (pure gather, writes every voxel)
    k_Atg_b<<<VB, 256>>>(theta, psf, slices);
    // 2: sl = A(x0)        (pAp slot 15 = dummy)
    k_A<false><<<gridS, 256>>>(theta, psf, volume, 0, 15);
    // 3: r0 = b - At(sl); rr[0]
    k_Atg_init<<<VB, 256>>>(theta, psf);

    // CG iterations; p is implicit in k_A (p_it = r + beta*p_prev)
    for (int it = 0; it < N_ITER; it++) {
        if (it == 0) k_A<false><<<gridS, 256>>>(theta, psf, r, 0,  0);
        else         k_A<true ><<<gridS, 256>>>(theta, psf, r, it, it);
        if (it == 0) k_Atg_xr<false><<<VB, 256>>>(theta, psf, 0);
        else         k_Atg_xr<true ><<<VB, 256>>>(theta, psf, it);
    }

    k_relu_out<<<VB, 256>>>(out);
    (void)out_size;
}

// round 6
// speedup vs baseline: 1.2859x; 1.2859x over previous
#include <cuda_runtime.h>
#include <math.h>

// ---------------------------------------------------------------------------
// Problem constants
// ---------------------------------------------------------------------------
#define DW 128
#define DH 128
#define DD 128
#define NV (DW*DH*DD)          // 2097152 voxels
#define NS 16
#define HSL 128
#define WSL 128
#define PIX (HSL*WSL)
#define RES 1.5f
#define N_ITER 10

// ---------------------------------------------------------------------------
// Persistent state (device globals -> no allocations anywhere)
// ---------------------------------------------------------------------------
__device__ float g_b[NV];
__device__ float g_x[NV];
__device__ float g_r[NV];
__device__ float g_p[NV];          // materialized p (p_prev for next iter)
__device__ float g_Ap[NV];
// per-iteration CG scalars (double accumulators)
__device__ double g_pAp[16];
__device__ double g_rr[16];

// ---------------------------------------------------------------------------
// Block reduction -> atomicAdd(double)
// ---------------------------------------------------------------------------
__device__ __forceinline__ void reduce_add(double val, double* target)
{
    #pragma unroll
    for (int o = 16; o > 0; o >>= 1)
        val += __shfl_down_sync(0xffffffffu, val, o);
    __shared__ double sm[32];
    int lane = threadIdx.x & 31, wid = threadIdx.x >> 5;
    if (lane == 0) sm[wid] = val;
    __syncthreads();
    if (wid == 0) {
        val = (lane < (int)(blockDim.x >> 5)) ? sm[lane] : 0.0;
        #pragma unroll
        for (int o = 16; o > 0; o >>= 1)
            val += __shfl_down_sync(0xffffffffu, val, o);
        if (lane == 0) atomicAdd(target, val);
    }
}

// ---------------------------------------------------------------------------
// Vector RED helper: 8B-aligned pair add (sm_90+)
// ---------------------------------------------------------------------------
__device__ __forceinline__ void red2(float* p2, float a, float b)
{
    asm volatile("red.global.add.v2.f32 [%0], {%1, %2};"
                 :: "l"(p2), "f"(a), "f"(b) : "memory");
}

// ---------------------------------------------------------------------------
// Forward gather of one PSF tap.  Implicit input vector:
//   v = v1 + beta * g_p   (HASB) or just v1.
// Matches reference _corners semantics (OOB corners contribute 0).
// ---------------------------------------------------------------------------
template<bool HASB>
__device__ __forceinline__ float fetch(const float* __restrict__ v1, float beta, int idx)
{
    float v = __ldg(v1 + idx);
    if (HASB) v += beta * __ldg(&g_p[idx]);
    return v;
}

template<bool HASB>
__device__ __forceinline__ float gather_tap(const float* __restrict__ v1, float beta,
                                            float px, float py, float pz)
{
    if (px <= -1.f || px >= 128.f || py <= -1.f || py >= 128.f ||
        pz <= -1.f || pz >= 128.f)
        return 0.f;

    float xf = floorf(px), yf = floorf(py), zf = floorf(pz);
    int ix = (int)xf, iy = (int)yf, iz = (int)zf;
    float fx = px - xf, fy = py - yf, fz = pz - zf;
    float gx = 1.f - fx, gy = 1.f - fy, gz = 1.f - fz;

    if (ix >= 0 && ix < DW-1 && iy >= 0 && iy < DH-1 && iz >= 0 && iz < DD-1) {
        int b0 = (iz*DH + iy)*DW + ix;
        int b1 = b0 + DH*DW;
        float v000 = fetch<HASB>(v1, beta, b0),      v100 = fetch<HASB>(v1, beta, b0+1);
        float v010 = fetch<HASB>(v1, beta, b0+DW),   v110 = fetch<HASB>(v1, beta, b0+DW+1);
        float v001 = fetch<HASB>(v1, beta, b1),      v101 = fetch<HASB>(v1, beta, b1+1);
        float v011 = fetch<HASB>(v1, beta, b1+DW),   v111 = fetch<HASB>(v1, beta, b1+DW+1);
        return gz*(gy*(gx*v000 + fx*v100) + fy*(gx*v010 + fx*v110))
             + fz*(gy*(gx*v001 + fx*v101) + fy*(gx*v011 + fx*v111));
    }

    float acc = 0.f;
    #pragma unroll
    for (int dz = 0; dz < 2; dz++)
    #pragma unroll
    for (int dy = 0; dy < 2; dy++)
    #pragma unroll
    for (int dx = 0; dx < 2; dx++) {
        int X = ix + dx, Y = iy + dy, Z = iz + dz;
        if (X >= 0 && X < DW && Y >= 0 && Y < DH && Z >= 0 && Z < DD) {
            float w = (dx ? fx : gx) * (dy ? fy : gy) * (dz ? fz : gz);
            acc += w * fetch<HASB>(v1, beta, (Z*DH + Y)*DW + X);
        }
    }
    return acc;
}

// ---------------------------------------------------------------------------
// Scatter-add of one PSF tap (exact adjoint of gather_tap).
// Interior fast path uses red.v2 on 8B-aligned corner pairs.
// ---------------------------------------------------------------------------
__device__ __forceinline__ void scatter_tap(float* __restrict__ v,
                                            float px, float py, float pz, float c)
{
    if (px <= -1.f || px >= 128.f || py <= -1.f || py >= 128.f ||
        pz <= -1.f || pz >= 128.f)
        return;

    float xf = floorf(px), yf = floorf(py), zf = floorf(pz);
    int ix = (int)xf, iy = (int)yf, iz = (int)zf;
    float fx = px - xf, fy = py - yf, fz = pz - zf;
    float gx = 1.f - fx, gy = 1.f - fy, gz = 1.f - fz;

    if (ix >= 0 && ix < DW-1 && iy >= 0 && iy < DH-1 && iz >= 0 && iz < DD-1) {
        float* b0 = v + ((iz*DH + iy)*DW + ix);
        float* b1 = b0 + DH*DW;
        float w00 = c*gz*gy, w01 = c*gz*fy, w10 = c*fz*gy, w11 = c*fz*fy;
        if (!(ix & 1)) {
            red2(b0,      w00*gx, w00*fx);
            red2(b0+DW,   w01*gx, w01*fx);
            red2(b1,      w10*gx, w10*fx);
            red2(b1+DW,   w11*gx, w11*fx);
        } else {
            atomicAdd(b0,       w00*gx);
            atomicAdd(b0+1,     w00*fx);
            atomicAdd(b0+DW,    w01*gx);
            atomicAdd(b0+DW+1,  w01*fx);
            atomicAdd(b1,       w10*gx);
            atomicAdd(b1+1,     w10*fx);
            atomicAdd(b1+DW,    w11*gx);
            atomicAdd(b1+DW+1,  w11*fx);
        }
        return;
    }

    #pragma unroll
    for (int dz = 0; dz < 2; dz++)
    #pragma unroll
    for (int dy = 0; dy < 2; dy++)
    #pragma unroll
    for (int dx = 0; dx < 2; dx++) {
        int X = ix + dx, Y = iy + dy, Z = iz + dz;
        if (X >= 0 && X < DW && Y >= 0 && Y < DH && Z >= 0 && Z < DD) {
            float w = (dx ? fx : gx) * (dy ? fy : gy) * (dz ? fz : gz);
            atomicAdd(v + ((Z*DH + Y)*DW + X), c*w);
        }
    }
}

// ---------------------------------------------------------------------------
// Per-slice PSF tap constants into shared memory.
// ---------------------------------------------------------------------------
__device__ __forceinline__ void load_slice_consts(const float* __restrict__ theta,
                                                  const float* __restrict__ psf,
                                                  int n, float sR[9],
                                                  float sC[27][3], float sPsf[27])
{
    int t = threadIdx.x;
    if (t < 9) sR[t] = theta[n*12 + (t/3)*4 + (t%3)];
    __syncthreads();
    if (t < 27) {
        float ox = (float)(t % 3)       - 1.f;
        float oy = (float)((t / 3) % 3) - 1.f;
        float oz = (float)(t / 9)       - 1.f;
        float tx = theta[n*12 + 3],  ty = theta[n*12 + 7],  tz = theta[n*12 + 11];
        sC[t][0] = sR[0]*ox + sR[1]*oy + sR[2]*oz + tx + 63.5f;
        sC[t][1] = sR[3]*ox + sR[4]*oy + sR[5]*oz + ty + 63.5f;
        sC[t][2] = sR[6]*ox + sR[7]*oy + sR[8]*oz + tz + 63.5f;
        sPsf[t]  = psf[t];
    }
    __syncthreads();
}

// ---------------------------------------------------------------------------
// Fused AtA: per pixel, gather sval = (A v)_pix from implicit v = v1 + b*g_p,
// accumulate pAp += sval^2 (== p.AtAp), then scatter sval*psf into g_Ap
// (g_Ap zeroed by the previous update kernel).
// grid = (64, 1, 16), block = 256.  ALL threads reach the reduction.
// ---------------------------------------------------------------------------
template<bool HASB>
__global__ void __launch_bounds__(256)
k_AtA(const float* __restrict__ theta, const float* __restrict__ psf,
      const float* __restrict__ v1, int beta_it, int pAp_slot)
{
    __shared__ float sR[9];
    __shared__ float sC[27][3];
    __shared__ float sPsf[27];
    int n = blockIdx.z;
    load_slice_consts(theta, psf, n, sR, sC, sPsf);

    float beta = 0.f;
    if (HASB) beta = (float)(g_rr[beta_it] / g_rr[beta_it - 1]);

    int pix = blockIdx.x * blockDim.x + threadIdx.x;
    int w = pix & (WSL-1);
    int h = pix >> 7;
    float u  = ((float)w - 63.5f) * RES;
    float vv = ((float)h - 63.5f) * RES;
    float bx = sR[0]*u + sR[1]*vv;
    float by = sR[3]*u + sR[4]*vv;
    float bz = sR[6]*u + sR[7]*vv;

    float sval = 0.f;
    // conservative whole-pixel reject: center tap (k=13) within margin 3
    float cx = bx + sC[13][0], cy = by + sC[13][1], cz = bz + sC[13][2];
    bool live = (cx > -3.f && cx < 130.f && cy > -3.f && cy < 130.f &&
                 cz > -3.f && cz < 130.f);
    if (live) {
        for (int k = 0; k < 27; k++)
            sval += sPsf[k] * gather_tap<HASB>(v1, beta,
                        bx + sC[k][0], by + sC[k][1], bz + sC[k][2]);
    }
    reduce_add((double)sval * (double)sval, &g_pAp[pAp_slot]);
    if (sval != 0.f) {
        for (int k = 0; k < 27; k++)
            scatter_tap(g_Ap, bx + sC[k][0], by + sC[k][1], bz + sC[k][2],
                        sval * sPsf[k]);
    }
}

// ---------------------------------------------------------------------------
// b = At(slices): scatter raw slice values (g_b zeroed by k_init).
// ---------------------------------------------------------------------------
__global__ void __launch_bounds__(256)
k_At_b(const float* __restrict__ theta, const float* __restrict__ psf,
       const float* __restrict__ slices)
{
    __shared__ float sR[9];
    __shared__ float sC[27][3];
    __shared__ float sPsf[27];
    int n = blockIdx.z;
    load_slice_consts(theta, psf, n, sR, sC, sPsf);

    int pix = blockIdx.x * blockDim.x + threadIdx.x;
    int w = pix & (WSL-1);
    int h = pix >> 7;
    float u  = ((float)w - 63.5f) * RES;
    float vv = ((float)h - 63.5f) * RES;
    float bx = sR[0]*u + sR[1]*vv;
    float by = sR[3]*u + sR[4]*vv;
    float bz = sR[6]*u + sR[7]*vv;

    float cx = bx + sC[13][0], cy = by + sC[13][1], cz = bz + sC[13][2];
    if (cx < -3.f || cx > 130.f || cy < -3.f || cy > 130.f ||
        cz < -3.f || cz > 130.f)
        return;

    float sval = slices[n * PIX + pix];
    for (int k = 0; k < 27; k++)
        scatter_tap(g_b, bx + sC[k][0], by + sC[k][1], bz + sC[k][2],
                    sval * sPsf[k]);
}

// ---------------------------------------------------------------------------
// Small fused kernels
// ---------------------------------------------------------------------------
// x = x0; zero b, Ap, scalar slots
__global__ void __launch_bounds__(256)
k_init(const float* __restrict__ volume)
{
    int i = blockIdx.x * blockDim.x + threadIdx.x;
    g_x[i]  = volume[i];
    g_b[i]  = 0.f;
    g_Ap[i] = 0.f;
    if (blockIdx.x == 0 && threadIdx.x < 16) {
        g_pAp[threadIdx.x] = 0.0;
        g_rr[threadIdx.x]  = 0.0;
    }
}

// r = b - Ap ; rr[0] += r.r ; Ap = 0 for first CG iteration
__global__ void __launch_bounds__(256)
k_init_rp()
{
    int i = blockIdx.x * blockDim.x + threadIdx.x;
    float rv = g_b[i] - g_Ap[i];
    g_r[i] = rv;
    g_Ap[i] = 0.f;
    reduce_add((double)rv * (double)rv, &g_rr[0]);
}

// Fused CG update for iteration it:
//   alpha = rr[it]/pAp[it]; p_cur = r + beta*p_prev (beta = rr[it]/rr[it-1]);
//   x += alpha*p_cur; p = p_cur; r -= alpha*Ap; rr[it+1] += r.r; Ap = 0
template<bool HASB>
__global__ void __launch_bounds__(256)
k_update(int it)
{
    float alpha = (float)(g_rr[it] / g_pAp[it]);
    int i = blockIdx.x * blockDim.x + threadIdx.x;
    float rv = g_r[i];
    float pc;
    if (HASB) {
        float beta = (float)(g_rr[it] / g_rr[it - 1]);
        pc = rv + beta * g_p[i];
    } else {
        pc = rv;
    }
    g_x[i] += alpha * pc;
    g_p[i] = pc;
    rv -= alpha * g_Ap[i];
    g_r[i] = rv;
    g_Ap[i] = 0.f;
    reduce_add((double)rv * (double)rv, &g_rr[it + 1]);
}

__global__ void __launch_bounds__(256)
k_relu_out(float* __restrict__ out)
{
    int i = blockIdx.x * blockDim.x + threadIdx.x;
    out[i] = fmaxf(g_x[i], 0.f);
}

// ---------------------------------------------------------------------------
// Host driver (graph-capturable: kernel launches only)
// ---------------------------------------------------------------------------
extern "C" void kernel_launch(void* const* d_in, const int* in_sizes, int n_in,
                              void* d_out, int out_size)
{
    const float *theta = nullptr, *slices = nullptr, *volume = nullptr, *psf = nullptr;
    for (int i = 0; i < n_in; i++) {
        switch (in_sizes[i]) {
            case NS*12:   theta  = (const float*)d_in[i]; break;
            case NS*PIX:  slices = (const float*)d_in[i]; break;
            case NV:      volume = (const float*)d_in[i]; break;
            case 27:      psf    = (const float*)d_in[i]; break;
            default: break;
        }
    }
    float* out = (float*)d_out;

    float *r;
    cudaGetSymbolAddress((void**)&r, g_r);

    const int VB = NV / 256;                       // 8192
    const dim3 gridS(PIX / 256, 1, NS);            // (64,1,16)

    // x = x0; zero b, Ap, scalars
    k_init<<<VB, 256>>>(volume);
    // b = At(slices)
    k_At_b<<<gridS, 256>>>(theta, psf, slices);
    // Ap = AtA(x0)  (pAp slot 15 = dummy)
    k_AtA<false><<<gridS, 256>>>(theta, psf, volume, 0, 15);
    // r0 = b - Ap; rr[0]; zero Ap
    k_init_rp<<<VB, 256>>>();

    // CG iterations; p is implicit in k_AtA (p_it = r + beta*p_prev)
    for (int it = 0; it < N_ITER; it++) {
        if (it == 0) {
            k_AtA<false><<<gridS, 256>>>(theta, psf, r, 0, 0);
            k_update<false><<<VB, 256>>>(0);
        } else {
            k_AtA<true ><<<gridS, 256>>>(theta, psf, r, it, it);
            k_update<true ><<<VB, 256>>>(it);
        }
    }

    k_relu_out<<<VB, 256>>>(out);
    (void)out_size;
}

// round 8
// speedup vs baseline: 2.2960x; 1.7855x over previous
#include <cuda_runtime.h>
#include <math.h>

// ---------------------------------------------------------------------------
// Problem constants
// ---------------------------------------------------------------------------
#define DW 128
#define DH 128
#define DD 128
#define NV (DW*DH*DD)          // 2097152 voxels
#define NS 16
#define HSL 128
#define WSL 128
#define PIX (HSL*WSL)
#define RES 1.5f
#define N_ITER 10

// ---------------------------------------------------------------------------
// Persistent state (device globals -> no allocations anywhere)
// ---------------------------------------------------------------------------
__device__ float g_b[NV];
__device__ float g_x[NV];
__device__ float g_r[NV];
__device__ float g_p[NV];
__device__ float g_Ap[NV];
// per-iteration CG scalars (double accumulators)
__device__ double g_pAp[16];
__device__ double g_rr[16];

// ---------------------------------------------------------------------------
// Block reduction -> atomicAdd(double)
// ---------------------------------------------------------------------------
__device__ __forceinline__ void reduce_add(double val, double* target)
{
    #pragma unroll
    for (int o = 16; o > 0; o >>= 1)
        val += __shfl_down_sync(0xffffffffu, val, o);
    __shared__ double sm[32];
    int lane = threadIdx.x & 31, wid = threadIdx.x >> 5;
    if (lane == 0) sm[wid] = val;
    __syncthreads();
    if (wid == 0) {
        val = (lane < (int)(blockDim.x >> 5)) ? sm[lane] : 0.0;
        #pragma unroll
        for (int o = 16; o > 0; o >>= 1)
            val += __shfl_down_sync(0xffffffffu, val, o);
        if (lane == 0) atomicAdd(target, val);
    }
}

// ---------------------------------------------------------------------------
// Forward gather of one PSF tap (OOB corners contribute 0, as in reference).
// ---------------------------------------------------------------------------
__device__ __forceinline__ float gather_tap(const float* __restrict__ v,
                                            float px, float py, float pz)
{
    if (px <= -1.f || px >= 128.f || py <= -1.f || py >= 128.f ||
        pz <= -1.f || pz >= 128.f)
        return 0.f;

    float xf = floorf(px), yf = floorf(py), zf = floorf(pz);
    int ix = (int)xf, iy = (int)yf, iz = (int)zf;
    float fx = px - xf, fy = py - yf, fz = pz - zf;
    float gx = 1.f - fx, gy = 1.f - fy, gz = 1.f - fz;

    if (ix >= 0 && ix < DW-1 && iy >= 0 && iy < DH-1 && iz >= 0 && iz < DD-1) {
        const float* b0 = v + ((iz*DH + iy)*DW + ix);
        const float* b1 = b0 + DH*DW;
        float v000 = __ldg(b0),      v100 = __ldg(b0+1);
        float v010 = __ldg(b0+DW),   v110 = __ldg(b0+DW+1);
        float v001 = __ldg(b1),      v101 = __ldg(b1+1);
        float v011 = __ldg(b1+DW),   v111 = __ldg(b1+DW+1);
        return gz*(gy*(gx*v000 + fx*v100) + fy*(gx*v010 + fx*v110))
             + fz*(gy*(gx*v001 + fx*v101) + fy*(gx*v011 + fx*v111));
    }

    float acc = 0.f;
    #pragma unroll
    for (int dz = 0; dz < 2; dz++)
    #pragma unroll
    for (int dy = 0; dy < 2; dy++)
    #pragma unroll
    for (int dx = 0; dx < 2; dx++) {
        int X = ix + dx, Y = iy + dy, Z = iz + dz;
        if (X >= 0 && X < DW && Y >= 0 && Y < DH && Z >= 0 && Z < DD) {
            float w = (dx ? fx : gx) * (dy ? fy : gy) * (dz ? fz : gz);
            acc += w * __ldg(v + ((Z*DH + Y)*DW + X));
        }
    }
    return acc;
}

// ---------------------------------------------------------------------------
// Scatter-add of one PSF tap (exact adjoint; uniform scalar REDs, no branch
// divergence in the interior path).
// ---------------------------------------------------------------------------
__device__ __forceinline__ void scatter_tap(float* __restrict__ v,
                                            float px, float py, float pz, float c)
{
    if (px <= -1.f || px >= 128.f || py <= -1.f || py >= 128.f ||
        pz <= -1.f || pz >= 128.f)
        return;

    float xf = floorf(px), yf = floorf(py), zf = floorf(pz);
    int ix = (int)xf, iy = (int)yf, iz = (int)zf;
    float fx = px - xf, fy = py - yf, fz = pz - zf;
    float gx = 1.f - fx, gy = 1.f - fy, gz = 1.f - fz;

    if (ix >= 0 && ix < DW-1 && iy >= 0 && iy < DH-1 && iz >= 0 && iz < DD-1) {
        float* b0 = v + ((iz*DH + iy)*DW + ix);
        float* b1 = b0 + DH*DW;
        float w00 = c*gz*gy, w01 = c*gz*fy, w10 = c*fz*gy, w11 = c*fz*fy;
        atomicAdd(b0,       w00*gx);
        atomicAdd(b0+1,     w00*fx);
        atomicAdd(b0+DW,    w01*gx);
        atomicAdd(b0+DW+1,  w01*fx);
        atomicAdd(b1,       w10*gx);
        atomicAdd(b1+1,     w10*fx);
        atomicAdd(b1+DW,    w11*gx);
        atomicAdd(b1+DW+1,  w11*fx);
        return;
    }

    #pragma unroll
    for (int dz = 0; dz < 2; dz++)
    #pragma unroll
    for (int dy = 0; dy < 2; dy++)
    #pragma unroll
    for (int dx = 0; dx < 2; dx++) {
        int X = ix + dx, Y = iy + dy, Z = iz + dz;
        if (X >= 0 && X < DW && Y >= 0 && Y < DH && Z >= 0 && Z < DD) {
            float w = (dx ? fx : gx) * (dy ? fy : gy) * (dz ? fz : gz);
            atomicAdd(v + ((Z*DH + Y)*DW + X), c*w);
        }
    }
}

// ---------------------------------------------------------------------------
// Per-slice PSF tap constants into shared memory.
// ---------------------------------------------------------------------------
__device__ __forceinline__ void load_slice_consts(const float* __restrict__ theta,
                                                  const float* __restrict__ psf,
                                                  int n, float sR[9],
                                                  float sC[27][3], float sPsf[27])
{
    int t = threadIdx.x;
    if (t < 9) sR[t] = theta[n*12 + (t/3)*4 + (t%3)];
    __syncthreads();
    if (t < 27) {
        float ox = (float)(t % 3)       - 1.f;
        float oy = (float)((t / 3) % 3) - 1.f;
        float oz = (float)(t / 9)       - 1.f;
        float tx = theta[n*12 + 3],  ty = theta[n*12 + 7],  tz = theta[n*12 + 11];
        sC[t][0] = sR[0]*ox + sR[1]*oy + sR[2]*oz + tx + 63.5f;
        sC[t][1] = sR[3]*ox + sR[4]*oy + sR[5]*oz + ty + 63.5f;
        sC[t][2] = sR[6]*ox + sR[7]*oy + sR[8]*oz + tz + 63.5f;
        sPsf[t]  = psf[t];
    }
    __syncthreads();
}

// ---------------------------------------------------------------------------
// Fused AtA: sval = (A v)_pix; pAp[slot] += sval^2 (== p.AtAp since
// pAp = |Ap|^2); scatter sval*psf into g_Ap (pre-zeroed).
// grid = (64, 1, 16), block = 256.  ALL threads reach the reduction.
// ---------------------------------------------------------------------------
__global__ void __launch_bounds__(256)
k_AtA(const float* __restrict__ theta, const float* __restrict__ psf,
      const float* __restrict__ v, int pAp_slot)
{
    __shared__ float sR[9];
    __shared__ float sC[27][3];
    __shared__ float sPsf[27];
    int n = blockIdx.z;
    load_slice_consts(theta, psf, n, sR, sC, sPsf);

    int pix = blockIdx.x * blockDim.x + threadIdx.x;
    int w = pix & (WSL-1);
    int h = pix >> 7;
    float u  = ((float)w - 63.5f) * RES;
    float vv = ((float)h - 63.5f) * RES;
    float bx = sR[0]*u + sR[1]*vv;
    float by = sR[3]*u + sR[4]*vv;
    float bz = sR[6]*u + sR[7]*vv;

    float sval = 0.f;
    // conservative whole-pixel reject: center tap (k=13) within margin 3
    float cx = bx + sC[13][0], cy = by + sC[13][1], cz = bz + sC[13][2];
    if (cx > -3.f && cx < 130.f && cy > -3.f && cy < 130.f &&
        cz > -3.f && cz < 130.f) {
        for (int k = 0; k < 27; k++)
            sval += sPsf[k] * gather_tap(v, bx + sC[k][0], by + sC[k][1],
                                            bz + sC[k][2]);
    }
    reduce_add((double)sval * (double)sval, &g_pAp[pAp_slot]);
    if (sval != 0.f) {
        for (int k = 0; k < 27; k++)
            scatter_tap(g_Ap, bx + sC[k][0], by + sC[k][1], bz + sC[k][2],
                        sval * sPsf[k]);
    }
}

// ---------------------------------------------------------------------------
// b = At(slices): scatter raw slice values into g_b (pre-zeroed).
// ---------------------------------------------------------------------------
__global__ void __launch_bounds__(256)
k_At_b(const float* __restrict__ theta, const float* __restrict__ psf,
       const float* __restrict__ slices)
{
    __shared__ float sR[9];
    __shared__ float sC[27][3];
    __shared__ float sPsf[27];
    int n = blockIdx.z;
    load_slice_consts(theta, psf, n, sR, sC, sPsf);

    int pix = blockIdx.x * blockDim.x + threadIdx.x;
    int w = pix & (WSL-1);
    int h = pix >> 7;
    float u  = ((float)w - 63.5f) * RES;
    float vv = ((float)h - 63.5f) * RES;
    float bx = sR[0]*u + sR[1]*vv;
    float by = sR[3]*u + sR[4]*vv;
    float bz = sR[6]*u + sR[7]*vv;

    float cx = bx + sC[13][0], cy = by + sC[13][1], cz = bz + sC[13][2];
    if (cx < -3.f || cx > 130.f || cy < -3.f || cy > 130.f ||
        cz < -3.f || cz > 130.f)
        return;

    float sval = slices[n * PIX + pix];
    for (int k = 0; k < 27; k++)
        scatter_tap(g_b, bx + sC[k][0], by + sC[k][1], bz + sC[k][2],
                    sval * sPsf[k]);
}

// ---------------------------------------------------------------------------
// float4 elementwise kernels (all volumes L2-resident; vectorize for MLP)
// grid = NV/4/256 = 2048 blocks
// ---------------------------------------------------------------------------
#define F4(ptr) (reinterpret_cast<float4*>(ptr))
#define CF4(ptr) (reinterpret_cast<const float4*>(ptr))

// zero b, Ap, scalar slots
__global__ void __launch_bounds__(256)
k_zero()
{
    int i = blockIdx.x * blockDim.x + threadIdx.x;
    float4 z = make_float4(0.f, 0.f, 0.f, 0.f);
    F4(g_b)[i]  = z;
    F4(g_Ap)[i] = z;
    if (blockIdx.x == 0 && threadIdx.x < 16) {
        g_pAp[threadIdx.x] = 0.0;
        g_rr[threadIdx.x]  = 0.0;
    }
}

__global__ void __launch_bounds__(256)
k_copy_x(const float* __restrict__ volume)
{
    int i = blockIdx.x * blockDim.x + threadIdx.x;
    F4(g_x)[i] = CF4(volume)[i];
}

// r = b - Ap ; p = r ; rr[0] += r.r ; Ap = 0
__global__ void __launch_bounds__(256)
k_init_rp()
{
    int i = blockIdx.x * blockDim.x + threadIdx.x;
    float4 b4  = F4(g_b)[i];
    float4 a4  = F4(g_Ap)[i];
    float4 r4 = make_float4(b4.x - a4.x, b4.y - a4.y, b4.z - a4.z, b4.w - a4.w);
    F4(g_r)[i] = r4;
    F4(g_p)[i] = r4;
    F4(g_Ap)[i] = make_float4(0.f, 0.f, 0.f, 0.f);
    double v = (double)r4.x*r4.x + (double)r4.y*r4.y
             + (double)r4.z*r4.z + (double)r4.w*r4.w;
    reduce_add(v, &g_rr[0]);
}

// alpha = rr[it]/pAp[it]; x += alpha p; r -= alpha Ap; rr[it+1] += r.r; Ap = 0
__global__ void __launch_bounds__(256)
k_upA(int it)
{
    float alpha = (float)(g_rr[it] / g_pAp[it]);
    int i = blockIdx.x * blockDim.x + threadIdx.x;
    float4 p4 = F4(g_p)[i];
    float4 a4 = F4(g_Ap)[i];
    float4 x4 = F4(g_x)[i];
    float4 r4 = F4(g_r)[i];
    x4.x += alpha*p4.x; x4.y += alpha*p4.y; x4.z += alpha*p4.z; x4.w += alpha*p4.w;
    r4.x -= alpha*a4.x; r4.y -= alpha*a4.y; r4.z -= alpha*a4.z; r4.w -= alpha*a4.w;
    F4(g_x)[i] = x4;
    F4(g_r)[i] = r4;
    F4(g_Ap)[i] = make_float4(0.f, 0.f, 0.f, 0.f);
    double v = (double)r4.x*r4.x + (double)r4.y*r4.y
             + (double)r4.z*r4.z + (double)r4.w*r4.w;
    reduce_add(v, &g_rr[it + 1]);
}

// beta = rr[it+1]/rr[it]; p = r + beta p
__global__ void __launch_bounds__(256)
k_upP(int it)
{
    float beta = (float)(g_rr[it + 1] / g_rr[it]);
    int i = blockIdx.x * blockDim.x + threadIdx.x;
    float4 r4 = F4(g_r)[i];
    float4 p4 = F4(g_p)[i];
    F4(g_p)[i] = make_float4(r4.x + beta*p4.x, r4.y + beta*p4.y,
                             r4.z + beta*p4.z, r4.w + beta*p4.w);
}

__global__ void __launch_bounds__(256)
k_relu_out(float* __restrict__ out)
{
    int i = blockIdx.x * blockDim.x + threadIdx.x;
    float4 x4 = F4(g_x)[i];
    F4(out)[i] = make_float4(fmaxf(x4.x, 0.f), fmaxf(x4.y, 0.f),
                             fmaxf(x4.z, 0.f), fmaxf(x4.w, 0.f));
}

// ---------------------------------------------------------------------------
// Host driver (graph-capturable: kernel launches only)
// ---------------------------------------------------------------------------
extern "C" void kernel_launch(void* const* d_in, const int* in_sizes, int n_in,
                              void* d_out, int out_size)
{
    const float *theta = nullptr, *slices = nullptr, *volume = nullptr, *psf = nullptr;
    for (int i = 0; i < n_in; i++) {
        switch (in_sizes[i]) {
            case NS*12:   theta  = (const float*)d_in[i]; break;
            case NS*PIX:  slices = (const float*)d_in[i]; break;
            case NV:      volume = (const float*)d_in[i]; break;
            case 27:      psf    = (const float*)d_in[i]; break;
            default: break;
        }
    }
    float* out = (float*)d_out;

    float *p;
    cudaGetSymbolAddress((void**)&p, g_p);

    const int V4B = NV / 4 / 256;                  // 2048
    const dim3 gridS(PIX / 256, 1, NS);            // (64,1,16)

    // Launch #4 is what ncu captures -> make it k_AtA.
    k_zero<<<V4B, 256>>>();                          // 1: zero b, Ap, scalars
    k_At_b<<<gridS, 256>>>(theta, psf, slices);      // 2: b = At(slices)
    k_copy_x<<<V4B, 256>>>(volume);                  // 3: x = x0
    k_AtA<<<gridS, 256>>>(theta, psf, volume, 15);   // 4: Ap = AtA(x0)  [profiled]
    k_init_rp<<<V4B, 256>>>();                       // 5: r = p = b-Ap; rr[0]; Ap=0

    for (int it = 0; it < N_ITER; it++) {
        k_AtA<<<gridS, 256>>>(theta, psf, p, it);    // Ap = AtA(p); pAp[it]
        k_upA<<<V4B, 256>>>(it);                     // x, r, rr[it+1]; Ap=0
        if (it < N_ITER - 1)
            k_upP<<<V4B, 256>>>(it);                 // p = r + beta p
    }

    k_relu_out<<<V4B, 256>>>(out);
    (void)out_size;
}